// round 16
// baseline (speedup 1.0000x reference)
#include <cuda_runtime.h>
#include <cuda_fp16.h>
#include <math.h>
#include <stdint.h>

#define BB 2
#define SS 2048
#define HH 16
#define DD 128
#define HID (HH*DD)
#define SM_SCALE_L2E 0.12751649736230442f   /* (1/sqrt(128)) * log2(e) */
#define ATTN_GRID 592
#define N_ITEMS 1024

// ---------------- scratch (no allocation allowed) ----------------
__device__ signed char g_k8[(size_t)BB*HH*SS*DD];
__device__ __half      g_v16[(size_t)BB*HH*SS*DD];
__device__ float g_kscale[BB*HH*(SS/64)];
__device__ float g_vmean[BB*HH*DD];
__device__ float g_kpart[BB*HH*16*DD];
__device__ float g_vpart[BB*HH*16*DD];
__device__ int   g_wq;

// ---------------- block absmax (256 threads / 8 warps) ----------------
__device__ __forceinline__ float block_absmax(float v, float* red){
  #pragma unroll
  for (int o = 16; o > 0; o >>= 1)
    v = fmaxf(v, __shfl_xor_sync(0xffffffffu, v, o));
  int w = threadIdx.x >> 5;
  if ((threadIdx.x & 31) == 0) red[w] = v;
  __syncthreads();
  float r = red[0];
  #pragma unroll
  for (int i = 1; i < 8; i++) r = fmaxf(r, red[i]);
  return r;
}

// ---------------- K0: k/v mean partials (float4, 4 chains, in-block reduce) ----------------
__global__ void __launch_bounds__(256)
pre_k0(const float* __restrict__ k, const float* __restrict__ v){
  __shared__ float4 sred[2][8][32];   // [kv][rowgroup][colgroup] = 8KB
  int bh = blockIdx.y, bx = blockIdx.x;      // bx < 16 (128 rows per block)
  int b = bh >> 4, h = bh & 15;
  int t = threadIdx.x;
  if (bx == 0 && bh == 0 && t == 0) g_wq = ATTN_GRID;   // reset work queue every replay
  const int cg = t & 31;     // float4 column group (4 channels)
  const int rg = t >> 5;     // 8 row groups of 16 rows
  size_t base = ((size_t)b*SS + (size_t)bx*128 + (size_t)rg*16)*HID + h*DD + cg*4;
  float4 ka0 = {0,0,0,0}, ka1 = {0,0,0,0}, va0 = {0,0,0,0}, va1 = {0,0,0,0};
  #pragma unroll
  for (int r2 = 0; r2 < 16; r2 += 2){
    float4 xk0 = *(const float4*)(k + base + (size_t)r2*HID);
    float4 xv0 = *(const float4*)(v + base + (size_t)r2*HID);
    float4 xk1 = *(const float4*)(k + base + (size_t)(r2+1)*HID);
    float4 xv1 = *(const float4*)(v + base + (size_t)(r2+1)*HID);
    ka0.x += xk0.x; ka0.y += xk0.y; ka0.z += xk0.z; ka0.w += xk0.w;
    va0.x += xv0.x; va0.y += xv0.y; va0.z += xv0.z; va0.w += xv0.w;
    ka1.x += xk1.x; ka1.y += xk1.y; ka1.z += xk1.z; ka1.w += xk1.w;
    va1.x += xv1.x; va1.y += xv1.y; va1.z += xv1.z; va1.w += xv1.w;
  }
  ka0.x += ka1.x; ka0.y += ka1.y; ka0.z += ka1.z; ka0.w += ka1.w;
  va0.x += va1.x; va0.y += va1.y; va0.z += va1.z; va0.w += va1.w;
  sred[0][rg][cg] = ka0;
  sred[1][rg][cg] = va0;
  __syncthreads();
  if (t < 64){
    int kv = t >> 5, cg2 = t & 31;
    float4 s = sred[kv][0][cg2];
    #pragma unroll
    for (int g = 1; g < 8; g++){
      float4 x = sred[kv][g][cg2];
      s.x += x.x; s.y += x.y; s.z += x.z; s.w += x.w;
    }
    float* dst = kv ? g_vpart : g_kpart;
    *(float4*)(dst + ((size_t)(bh*16 + bx))*DD + cg2*4) = s;
  }
}

// ---------------- K1: quant_k (bx<32) + smooth_v (bx>=32); means in-block ----------------
__global__ void __launch_bounds__(256)
pre_k2(const float* __restrict__ k, const float* __restrict__ v){
  __shared__ float smean[128];
  int bh = blockIdx.y, bx = blockIdx.x;
  int b = bh >> 4, h = bh & 15;
  int t = threadIdx.x;
  if (t < 128){
    const float* part = (bx < 32) ? g_kpart : g_vpart;
    float a = 0.f;
    #pragma unroll
    for (int c = 0; c < 16; c++) a += part[(bh*16 + c)*DD + t];
    smean[t] = a / (float)SS;
    if (bx == 32) g_vmean[bh*DD + t] = smean[t];
  }
  __syncthreads();
  if (bx < 32){
    __shared__ float red[8];
    int g = bx;
    size_t inbase = ((size_t)b*SS + (size_t)g*64)*HID + h*DD;
    float4 vals[8]; float amax = 0.f;
    #pragma unroll
    for (int i = 0; i < 8; i++){
      int f4 = t + i*256;
      int row = f4 >> 5, c4 = f4 & 31;
      float4 x = *(const float4*)(k + inbase + (size_t)row*HID + c4*4);
      x.x -= smean[c4*4]; x.y -= smean[c4*4+1]; x.z -= smean[c4*4+2]; x.w -= smean[c4*4+3];
      vals[i] = x;
      amax = fmaxf(amax, fmaxf(fmaxf(fabsf(x.x), fabsf(x.y)), fmaxf(fabsf(x.z), fabsf(x.w))));
    }
    amax = block_absmax(amax, red);
    float scale = fmaxf(amax / 127.0f, 1e-8f);
    size_t obase = ((size_t)bh*SS + (size_t)g*64)*DD;
    #pragma unroll
    for (int i = 0; i < 8; i++){
      int f4 = t + i*256;
      int row = f4 >> 5, c4 = f4 & 31;
      char4 o;
      o.x = (signed char)(int)fminf(fmaxf(rintf(vals[i].x / scale), -127.f), 127.f);
      o.y = (signed char)(int)fminf(fmaxf(rintf(vals[i].y / scale), -127.f), 127.f);
      o.z = (signed char)(int)fminf(fmaxf(rintf(vals[i].z / scale), -127.f), 127.f);
      o.w = (signed char)(int)fminf(fmaxf(rintf(vals[i].w / scale), -127.f), 127.f);
      *(char4*)(g_k8 + obase + (size_t)row*DD + c4*4) = o;
    }
    if (t == 0) g_kscale[bh*32 + g] = scale;
  } else {
    int g = bx - 32;
    size_t inbase = ((size_t)b*SS + (size_t)g*64)*HID + h*DD;
    size_t obase  = ((size_t)bh*SS + (size_t)g*64)*DD;
    #pragma unroll
    for (int i = 0; i < 8; i++){
      int f4 = t + i*256;
      int row = f4 >> 5, c4 = f4 & 31;
      float4 x = *(const float4*)(v + inbase + (size_t)row*HID + c4*4);
      __half2 h0 = __floats2half2_rn(x.x - smean[c4*4],   x.y - smean[c4*4+1]);
      __half2 h1 = __floats2half2_rn(x.z - smean[c4*4+2], x.w - smean[c4*4+3]);
      uint2 o; o.x = *(uint32_t*)&h0; o.y = *(uint32_t*)&h1;
      *(uint2*)(g_v16 + obase + (size_t)row*DD + c4*4) = o;
    }
  }
}

// ---------------- MMA helpers ----------------
__device__ __forceinline__ void mma16816(float c[4], const uint32_t a[4], uint32_t b0, uint32_t b1){
  asm volatile(
    "mma.sync.aligned.m16n8k16.row.col.f32.f16.f16.f32 "
    "{%0,%1,%2,%3}, {%4,%5,%6,%7}, {%8,%9}, {%0,%1,%2,%3};\n"
    : "+f"(c[0]), "+f"(c[1]), "+f"(c[2]), "+f"(c[3])
    : "r"(a[0]), "r"(a[1]), "r"(a[2]), "r"(a[3]), "r"(b0), "r"(b1));
}
__device__ __forceinline__ void mma_s8(int c[4], const uint32_t a[4], uint32_t b0, uint32_t b1){
  asm volatile(
    "mma.sync.aligned.m16n8k32.row.col.s32.s8.s8.s32 "
    "{%0,%1,%2,%3}, {%4,%5,%6,%7}, {%8,%9}, {%0,%1,%2,%3};\n"
    : "+r"(c[0]), "+r"(c[1]), "+r"(c[2]), "+r"(c[3])
    : "r"(a[0]), "r"(a[1]), "r"(a[2]), "r"(a[3]), "r"(b0), "r"(b1));
}
__device__ __forceinline__ void ldmx4(uint32_t& t0, uint32_t& t1, uint32_t& t2, uint32_t& t3, uint32_t addr){
  asm volatile("ldmatrix.sync.aligned.m8n8.x4.shared.b16 {%0,%1,%2,%3}, [%4];\n"
    : "=r"(t0), "=r"(t1), "=r"(t2), "=r"(t3) : "r"(addr));
}
__device__ __forceinline__ void ldmx4t(uint32_t& t0, uint32_t& t1, uint32_t& t2, uint32_t& t3, uint32_t addr){
  asm volatile("ldmatrix.sync.aligned.m8n8.x4.trans.shared.b16 {%0,%1,%2,%3}, [%4];\n"
    : "=r"(t0), "=r"(t1), "=r"(t2), "=r"(t3) : "r"(addr));
}
#define CP16(dst, src) asm volatile("cp.async.cg.shared.global [%0], [%1], 16;\n" :: "r"(dst), "l"(src) : "memory")

#define KPITCH 144
#define VPITCH 272
#define SK_OFF(st) ((st)*64*KPITCH)
#define SV_OFF(st) (2*64*KPITCH + (st)*64*VPITCH)
#define SMEM_TOTAL (2*64*KPITCH + 2*64*VPITCH)   // 53248

// ---------------- main attention kernel (persistent, 4 CTA/SM, single-barrier loop) ----------------
__global__ void __launch_bounds__(128, 4)
attn_kernel(const float* __restrict__ qsrc,
            const int* __restrict__ wlp, const int* __restrict__ wrp,
            float* __restrict__ out){
  extern __shared__ char smem[];
  __shared__ int s_next;
  __shared__ float qred[4];
  const uint32_t smem_b = (uint32_t)__cvta_generic_to_shared(smem);

  const int tid = threadIdx.x, wid = tid >> 5, lane = tid & 31;
  const int r   = lane >> 2, q2 = (lane & 3) * 2, c4 = (lane & 3) * 4;
  const int wl = *wlp, wr = *wrp;
  const int ldm_g = lane >> 3;
  const uint32_t kfrag_off = (uint32_t)(((ldm_g >> 1)*8 + (lane & 7))*KPITCH + (ldm_g & 1)*16);
  const int jrow = lane & 15;
  const int dsel = (lane & 16) ? 8 : 0;
  const int qrow = wid*16 + r;

  int wi = blockIdx.x;
  while (wi < N_ITEMS){
    const int q_ord = wi >> 5;
    const int bh = wi & 31;
    const int xq = (q_ord & 1) ? (16 + (q_ord >> 1)) : (15 - (q_ord >> 1));
    const int i0 = xq * 64;
    const int b = bh >> 4, h = bh & 15;

    const signed char* Kg = g_k8 + (size_t)bh*SS*DD;
    const __half*      Vg = g_v16 + (size_t)bh*SS*DD;

    int jlo = (wl >= 0) ? max(0, i0 - wl) : 0;
    int jhi = (wr >= 0) ? min(SS-1, i0 + 63 + wr) : SS-1;
    const int jloT = jlo & ~63;
    const int nt = ((jhi - jloT) >> 6) + 1;

    auto issue = [&](int st, int j0){
      uint32_t kb = smem_b + SK_OFF(st);
      const signed char* kg = Kg + (size_t)j0*128;
      #pragma unroll
      for (int c = tid; c < 512; c += 128){
        int row = c >> 3, seg = c & 7;
        CP16(kb + row*KPITCH + seg*16, kg + row*128 + seg*16);
      }
      uint32_t vb = smem_b + SV_OFF(st);
      const __half* vg = Vg + (size_t)j0*128;
      #pragma unroll
      for (int c = tid; c < 1024; c += 128){
        int row = c >> 4, seg = c & 15;
        CP16(vb + row*VPITCH + seg*16, (const char*)vg + row*256 + seg*16);
      }
      asm volatile("cp.async.commit_group;\n" ::: "memory");
    };

    issue(0, jloT);   // tile-0 load overlaps Q quantization below

    // ---- fused Q quantization: f32 gmem -> int8 afrag (bit-identical to ref) ----
    const float* row0 = qsrc + ((size_t)b*SS + i0 + qrow)*HID + h*DD;
    const float* row1 = row0 + (size_t)8*HID;
    float amax = 0.f;
    #pragma unroll
    for (int kc = 0; kc < 4; kc++){
      #pragma unroll
      for (int j = 0; j < 4; j++){
        const float* rp = (j & 1) ? row1 : row0;
        int col = kc*32 + c4 + ((j & 2) ? 16 : 0);
        float4 x = *(const float4*)(rp + col);
        amax = fmaxf(amax, fmaxf(fmaxf(fabsf(x.x), fabsf(x.y)), fmaxf(fabsf(x.z), fabsf(x.w))));
      }
    }
    #pragma unroll
    for (int o = 16; o > 0; o >>= 1)
      amax = fmaxf(amax, __shfl_xor_sync(0xffffffffu, amax, o));
    if (lane == 0) qred[wid] = amax;
    __syncthreads();
    const float qscale = fmaxf(fmaxf(qred[wid], qred[wid ^ 1]) / 127.0f, 1e-8f);
    uint32_t afrag[4][4];
    #pragma unroll
    for (int kc = 0; kc < 4; kc++){
      #pragma unroll
      for (int j = 0; j < 4; j++){
        const float* rp = (j & 1) ? row1 : row0;
        int col = kc*32 + c4 + ((j & 2) ? 16 : 0);
        float4 x = *(const float4*)(rp + col);   // L1-resident reload
        int b0 = (int)fminf(fmaxf(rintf(x.x / qscale), -127.f), 127.f);
        int b1 = (int)fminf(fmaxf(rintf(x.y / qscale), -127.f), 127.f);
        int b2 = (int)fminf(fmaxf(rintf(x.z / qscale), -127.f), 127.f);
        int b3 = (int)fminf(fmaxf(rintf(x.w / qscale), -127.f), 127.f);
        afrag[kc][j] = (uint32_t)(b0 & 0xff) | ((uint32_t)(b1 & 0xff) << 8)
                     | ((uint32_t)(b2 & 0xff) << 16) | ((uint32_t)(b3 & 0xff) << 24);
      }
    }

    const float qsl = qscale * SM_SCALE_L2E;
    const int i_r0 = i0 + qrow, i_r1 = i_r0 + 8;
    const int lo0 = (wl < 0) ? -0x40000000 : i_r0 - wl;
    const int hi0 = (wr < 0) ?  0x40000000 : i_r0 + wr;
    const int lo1 = (wl < 0) ? -0x40000000 : i_r1 - wl;
    const int hi1 = (wr < 0) ?  0x40000000 : i_r1 + wr;

    float of[16][4];
    #pragma unroll
    for (int n = 0; n < 16; n++){ of[n][0]=0.f; of[n][1]=0.f; of[n][2]=0.f; of[n][3]=0.f; }
    float m0 = -1e30f, m1 = -1e30f, l0 = 0.f, l1 = 0.f;

    float ksc = g_kscale[bh*(SS/64) + (jloT >> 6)];

    for (int it = 0; it < nt; it++){
      const int j0 = jloT + it*64;
      const int st = it & 1;
      // single-barrier pipeline: wait own tile -> barrier -> issue next -> compute
      asm volatile("cp.async.wait_group 0;\n" ::: "memory");
      __syncthreads();
      if (it + 1 < nt) issue(st ^ 1, j0 + 64);

      const float dq = qsl * ksc;
      if (it + 1 < nt) ksc = g_kscale[bh*(SS/64) + ((j0 + 64) >> 6)];

      // --- S = Q K^T (int8 MMA, exact); B-frags via ldmatrix.x4 ---
      int acc[8][4];
      #pragma unroll
      for (int n = 0; n < 8; n++){ acc[n][0]=0; acc[n][1]=0; acc[n][2]=0; acc[n][3]=0; }
      const uint32_t kfb = smem_b + SK_OFF(st) + kfrag_off;
      #pragma unroll
      for (int m = 0; m < 16; m++){
        const int kc = m >> 2, nfp = m & 3;
        uint32_t b0, b1, b2, b3;
        ldmx4(b0, b1, b2, b3, kfb + nfp*(16*KPITCH) + kc*32);
        mma_s8(acc[nfp*2    ], afrag[kc], b0, b1);
        mma_s8(acc[nfp*2 + 1], afrag[kc], b2, b3);
      }

      const bool full = ((wl < 0) || (j0 >= i0 + 63 - wl)) && ((wr < 0) || (j0 + 63 <= i0 + wr));

      // --- pass 1: row max (int domain on full tiles) ---
      float mt0, mt1;
      if (full){
        int iA0[4], iA1[4];
        #pragma unroll
        for (int p = 0; p < 4; p++){
          iA0[p] = max(max(acc[2*p][0], acc[2*p][1]), max(acc[2*p+1][0], acc[2*p+1][1]));
          iA1[p] = max(max(acc[2*p][2], acc[2*p][3]), max(acc[2*p+1][2], acc[2*p+1][3]));
        }
        mt0 = __int2float_rn(max(max(iA0[0], iA0[1]), max(iA0[2], iA0[3]))) * dq;
        mt1 = __int2float_rn(max(max(iA1[0], iA1[1]), max(iA1[2], iA1[3]))) * dq;
      } else {
        mt0 = -INFINITY; mt1 = -INFINITY;
        #pragma unroll
        for (int nf = 0; nf < 8; nf++){
          int jc = j0 + nf*8 + q2;
          float s00 = (jc   >= lo0 && jc   <= hi0) ? __int2float_rn(acc[nf][0]) * dq : -INFINITY;
          float s01 = (jc+1 >= lo0 && jc+1 <= hi0) ? __int2float_rn(acc[nf][1]) * dq : -INFINITY;
          float s10 = (jc   >= lo1 && jc   <= hi1) ? __int2float_rn(acc[nf][2]) * dq : -INFINITY;
          float s11 = (jc+1 >= lo1 && jc+1 <= hi1) ? __int2float_rn(acc[nf][3]) * dq : -INFINITY;
          mt0 = fmaxf(mt0, fmaxf(s00, s01));
          mt1 = fmaxf(mt1, fmaxf(s10, s11));
        }
      }
      mt0 = fmaxf(mt0, __shfl_xor_sync(0xffffffffu, mt0, 1));
      mt0 = fmaxf(mt0, __shfl_xor_sync(0xffffffffu, mt0, 2));
      mt1 = fmaxf(mt1, __shfl_xor_sync(0xffffffffu, mt1, 1));
      mt1 = fmaxf(mt1, __shfl_xor_sync(0xffffffffu, mt1, 2));

      const bool raise = (mt0 > m0) || (mt1 > m1);
      const float mn0 = fmaxf(m0, mt0), mn1 = fmaxf(m1, mt1);
      const float a0 = exp2f(m0 - mn0), a1 = exp2f(m1 - mn1);
      if (it > 0 && __ballot_sync(0xffffffffu, raise)){   // of==0 at it==0: rescale is a no-op, skip
        #pragma unroll
        for (int n = 0; n < 16; n++){
          of[n][0]*=a0; of[n][1]*=a0; of[n][2]*=a1; of[n][3]*=a1;
        }
      }

      // --- pass 2 (streamed): per kc-chunk exp+pack then PV ---
      const uint32_t svb = smem_b + SV_OFF(st);
      float t0 = 0.f, t1 = 0.f;
      #pragma unroll
      for (int kc = 0; kc < 4; kc++){
        float e0[4], e1[4];
        if (full){
          #pragma unroll
          for (int hnf = 0; hnf < 2; hnf++){
            const int nf = 2*kc + hnf;
            e0[2*hnf  ] = exp2f(fmaf(__int2float_rn(acc[nf][0]), dq, -mn0));
            e0[2*hnf+1] = exp2f(fmaf(__int2float_rn(acc[nf][1]), dq, -mn0));
            e1[2*hnf  ] = exp2f(fmaf(__int2float_rn(acc[nf][2]), dq, -mn1));
            e1[2*hnf+1] = exp2f(fmaf(__int2float_rn(acc[nf][3]), dq, -mn1));
          }
        } else {
          #pragma unroll
          for (int hnf = 0; hnf < 2; hnf++){
            const int nf = 2*kc + hnf;
            int jc = j0 + nf*8 + q2;
            float s00 = (jc   >= lo0 && jc   <= hi0) ? __int2float_rn(acc[nf][0]) * dq : -INFINITY;
            float s01 = (jc+1 >= lo0 && jc+1 <= hi0) ? __int2float_rn(acc[nf][1]) * dq : -INFINITY;
            float s10 = (jc   >= lo1 && jc   <= hi1) ? __int2float_rn(acc[nf][2]) * dq : -INFINITY;
            float s11 = (jc+1 >= lo1 && jc+1 <= hi1) ? __int2float_rn(acc[nf][3]) * dq : -INFINITY;
            e0[2*hnf  ] = exp2f(s00 - mn0);
            e0[2*hnf+1] = exp2f(s01 - mn0);
            e1[2*hnf  ] = exp2f(s10 - mn1);
            e1[2*hnf+1] = exp2f(s11 - mn1);
          }
        }
        t0 += (e0[0] + e0[1]) + (e0[2] + e0[3]);
        t1 += (e1[0] + e1[1]) + (e1[2] + e1[3]);
        uint32_t pfrag[4];
        {
          __half2 p0 = __floats2half2_rn(e0[0], e0[1]);
          __half2 p1 = __floats2half2_rn(e1[0], e1[1]);
          __half2 p2 = __floats2half2_rn(e0[2], e0[3]);
          __half2 p3 = __floats2half2_rn(e1[2], e1[3]);
          pfrag[0] = *(uint32_t*)&p0; pfrag[1] = *(uint32_t*)&p1;
          pfrag[2] = *(uint32_t*)&p2; pfrag[3] = *(uint32_t*)&p3;
        }
        #pragma unroll
        for (int dc = 0; dc < 8; dc++){
          uint32_t addr = svb + (kc*16 + jrow)*VPITCH + (dc*16 + dsel)*2;
          uint32_t v0, v1, v2, v3;
          ldmx4t(v0, v1, v2, v3, addr);
          mma16816(of[dc*2    ], pfrag, v0, v1);
          mma16816(of[dc*2 + 1], pfrag, v2, v3);
        }
      }
      l0 = l0*a0 + t0; l1 = l1*a1 + t1;
      m0 = mn0; m1 = mn1;
    }

    // --- epilogue: reduce l over quad, normalize, f16-round, add v_mean ---
    l0 += __shfl_xor_sync(0xffffffffu, l0, 1);
    l0 += __shfl_xor_sync(0xffffffffu, l0, 2);
    l1 += __shfl_xor_sync(0xffffffffu, l1, 1);
    l1 += __shfl_xor_sync(0xffffffffu, l1, 2);
    float inv0 = 1.0f / l0, inv1 = 1.0f / l1;
    float* ob = out + ((size_t)b*SS)*HID + h*DD;
    const float* vm = g_vmean + bh*DD;
    #pragma unroll
    for (int n = 0; n < 16; n++){
      int d0 = n*8 + q2;
      float2 o0, o1;
      o0.x = __half2float(__float2half_rn(of[n][0]*inv0)) + vm[d0];
      o0.y = __half2float(__float2half_rn(of[n][1]*inv0)) + vm[d0+1];
      o1.x = __half2float(__float2half_rn(of[n][2]*inv1)) + vm[d0];
      o1.y = __half2float(__float2half_rn(of[n][3]*inv1)) + vm[d0+1];
      *(float2*)(ob + (size_t)i_r0*HID + d0) = o0;
      *(float2*)(ob + (size_t)i_r1*HID + d0) = o1;
    }

    // --- grab next work item (single barrier: covers smem-reuse safety + s_next visibility) ---
    if (tid == 0) s_next = atomicAdd(&g_wq, 1);
    __syncthreads();
    wi = s_next;
  }
}

// ---------------- launch ----------------
extern "C" void kernel_launch(void* const* d_in, const int* in_sizes, int n_in,
                              void* d_out, int out_size){
  const float* q = (const float*)d_in[0];
  const float* k = (const float*)d_in[1];
  const float* v = (const float*)d_in[2];
  const int* wl  = (const int*)d_in[3];
  const int* wr  = (const int*)d_in[4];
  float* out = (float*)d_out;

  cudaFuncSetAttribute(attn_kernel, cudaFuncAttributeMaxDynamicSharedMemorySize, SMEM_TOTAL);

  pre_k0<<<dim3(16, BB*HH), 256>>>(k, v);
  pre_k2<<<dim3(64, BB*HH), 256>>>(k, v);
  attn_kernel<<<ATTN_GRID, 128, SMEM_TOTAL>>>(q, wl, wr, out);
}

// round 17
// speedup vs baseline: 1.0105x; 1.0105x over previous
#include <cuda_runtime.h>
#include <cuda_fp16.h>
#include <math.h>
#include <stdint.h>

#define BB 2
#define SS 2048
#define HH 16
#define DD 128
#define HID (HH*DD)
#define SM_SCALE_L2E 0.12751649736230442f   /* (1/sqrt(128)) * log2(e) */
#define ATTN_GRID 592
#define N_ITEMS 1024

// ---------------- scratch (no allocation allowed) ----------------
__device__ signed char g_k8[(size_t)BB*HH*SS*DD];
__device__ __half      g_v16[(size_t)BB*HH*SS*DD];
__device__ float g_kscale[BB*HH*(SS/64)];
__device__ float g_vmean[BB*HH*DD];
__device__ float g_kpart[BB*HH*16*DD];
__device__ float g_vpart[BB*HH*16*DD];
__device__ int   g_wq;

// raw single-instruction exponential (base 2); args are <= 0 or -inf here
__device__ __forceinline__ float ex2(float x){
  float y;
  asm("ex2.approx.ftz.f32 %0, %1;" : "=f"(y) : "f"(x));
  return y;
}

// ---------------- block absmax (256 threads / 8 warps) ----------------
__device__ __forceinline__ float block_absmax(float v, float* red){
  #pragma unroll
  for (int o = 16; o > 0; o >>= 1)
    v = fmaxf(v, __shfl_xor_sync(0xffffffffu, v, o));
  int w = threadIdx.x >> 5;
  if ((threadIdx.x & 31) == 0) red[w] = v;
  __syncthreads();
  float r = red[0];
  #pragma unroll
  for (int i = 1; i < 8; i++) r = fmaxf(r, red[i]);
  return r;
}

// ---------------- K0: k/v mean partials (float4, 4 chains, in-block reduce) ----------------
__global__ void __launch_bounds__(256)
pre_k0(const float* __restrict__ k, const float* __restrict__ v){
  __shared__ float4 sred[2][8][32];   // [kv][rowgroup][colgroup] = 8KB
  int bh = blockIdx.y, bx = blockIdx.x;      // bx < 16 (128 rows per block)
  int b = bh >> 4, h = bh & 15;
  int t = threadIdx.x;
  if (bx == 0 && bh == 0 && t == 0) g_wq = ATTN_GRID;   // reset work queue every replay
  const int cg = t & 31;     // float4 column group (4 channels)
  const int rg = t >> 5;     // 8 row groups of 16 rows
  size_t base = ((size_t)b*SS + (size_t)bx*128 + (size_t)rg*16)*HID + h*DD + cg*4;
  float4 ka0 = {0,0,0,0}, ka1 = {0,0,0,0}, va0 = {0,0,0,0}, va1 = {0,0,0,0};
  #pragma unroll
  for (int r2 = 0; r2 < 16; r2 += 2){
    float4 xk0 = *(const float4*)(k + base + (size_t)r2*HID);
    float4 xv0 = *(const float4*)(v + base + (size_t)r2*HID);
    float4 xk1 = *(const float4*)(k + base + (size_t)(r2+1)*HID);
    float4 xv1 = *(const float4*)(v + base + (size_t)(r2+1)*HID);
    ka0.x += xk0.x; ka0.y += xk0.y; ka0.z += xk0.z; ka0.w += xk0.w;
    va0.x += xv0.x; va0.y += xv0.y; va0.z += xv0.z; va0.w += xv0.w;
    ka1.x += xk1.x; ka1.y += xk1.y; ka1.z += xk1.z; ka1.w += xk1.w;
    va1.x += xv1.x; va1.y += xv1.y; va1.z += xv1.z; va1.w += xv1.w;
  }
  ka0.x += ka1.x; ka0.y += ka1.y; ka0.z += ka1.z; ka0.w += ka1.w;
  va0.x += va1.x; va0.y += va1.y; va0.z += va1.z; va0.w += va1.w;
  sred[0][rg][cg] = ka0;
  sred[1][rg][cg] = va0;
  __syncthreads();
  if (t < 64){
    int kv = t >> 5, cg2 = t & 31;
    float4 s = sred[kv][0][cg2];
    #pragma unroll
    for (int g = 1; g < 8; g++){
      float4 x = sred[kv][g][cg2];
      s.x += x.x; s.y += x.y; s.z += x.z; s.w += x.w;
    }
    float* dst = kv ? g_vpart : g_kpart;
    *(float4*)(dst + ((size_t)(bh*16 + bx))*DD + cg2*4) = s;
  }
}

// ---------------- K1: quant_k (bx<32) + smooth_v (bx>=32); means in-block ----------------
__global__ void __launch_bounds__(256)
pre_k2(const float* __restrict__ k, const float* __restrict__ v){
  __shared__ float smean[128];
  int bh = blockIdx.y, bx = blockIdx.x;
  int b = bh >> 4, h = bh & 15;
  int t = threadIdx.x;
  if (t < 128){
    const float* part = (bx < 32) ? g_kpart : g_vpart;
    float a = 0.f;
    #pragma unroll
    for (int c = 0; c < 16; c++) a += part[(bh*16 + c)*DD + t];
    smean[t] = a / (float)SS;
    if (bx == 32) g_vmean[bh*DD + t] = smean[t];
  }
  __syncthreads();
  if (bx < 32){
    __shared__ float red[8];
    int g = bx;
    size_t inbase = ((size_t)b*SS + (size_t)g*64)*HID + h*DD;
    float4 vals[8]; float amax = 0.f;
    #pragma unroll
    for (int i = 0; i < 8; i++){
      int f4 = t + i*256;
      int row = f4 >> 5, c4 = f4 & 31;
      float4 x = *(const float4*)(k + inbase + (size_t)row*HID + c4*4);
      x.x -= smean[c4*4]; x.y -= smean[c4*4+1]; x.z -= smean[c4*4+2]; x.w -= smean[c4*4+3];
      vals[i] = x;
      amax = fmaxf(amax, fmaxf(fmaxf(fabsf(x.x), fabsf(x.y)), fmaxf(fabsf(x.z), fabsf(x.w))));
    }
    amax = block_absmax(amax, red);
    float scale = fmaxf(amax / 127.0f, 1e-8f);
    size_t obase = ((size_t)bh*SS + (size_t)g*64)*DD;
    #pragma unroll
    for (int i = 0; i < 8; i++){
      int f4 = t + i*256;
      int row = f4 >> 5, c4 = f4 & 31;
      char4 o;
      o.x = (signed char)(int)fminf(fmaxf(rintf(vals[i].x / scale), -127.f), 127.f);
      o.y = (signed char)(int)fminf(fmaxf(rintf(vals[i].y / scale), -127.f), 127.f);
      o.z = (signed char)(int)fminf(fmaxf(rintf(vals[i].z / scale), -127.f), 127.f);
      o.w = (signed char)(int)fminf(fmaxf(rintf(vals[i].w / scale), -127.f), 127.f);
      *(char4*)(g_k8 + obase + (size_t)row*DD + c4*4) = o;
    }
    if (t == 0) g_kscale[bh*32 + g] = scale;
  } else {
    int g = bx - 32;
    size_t inbase = ((size_t)b*SS + (size_t)g*64)*HID + h*DD;
    size_t obase  = ((size_t)bh*SS + (size_t)g*64)*DD;
    #pragma unroll
    for (int i = 0; i < 8; i++){
      int f4 = t + i*256;
      int row = f4 >> 5, c4 = f4 & 31;
      float4 x = *(const float4*)(v + inbase + (size_t)row*HID + c4*4);
      __half2 h0 = __floats2half2_rn(x.x - smean[c4*4],   x.y - smean[c4*4+1]);
      __half2 h1 = __floats2half2_rn(x.z - smean[c4*4+2], x.w - smean[c4*4+3]);
      uint2 o; o.x = *(uint32_t*)&h0; o.y = *(uint32_t*)&h1;
      *(uint2*)(g_v16 + obase + (size_t)row*DD + c4*4) = o;
    }
  }
}

// ---------------- MMA helpers ----------------
__device__ __forceinline__ void mma16816(float c[4], const uint32_t a[4], uint32_t b0, uint32_t b1){
  asm volatile(
    "mma.sync.aligned.m16n8k16.row.col.f32.f16.f16.f32 "
    "{%0,%1,%2,%3}, {%4,%5,%6,%7}, {%8,%9}, {%0,%1,%2,%3};\n"
    : "+f"(c[0]), "+f"(c[1]), "+f"(c[2]), "+f"(c[3])
    : "r"(a[0]), "r"(a[1]), "r"(a[2]), "r"(a[3]), "r"(b0), "r"(b1));
}
__device__ __forceinline__ void mma_s8(int c[4], const uint32_t a[4], uint32_t b0, uint32_t b1){
  asm volatile(
    "mma.sync.aligned.m16n8k32.row.col.s32.s8.s8.s32 "
    "{%0,%1,%2,%3}, {%4,%5,%6,%7}, {%8,%9}, {%0,%1,%2,%3};\n"
    : "+r"(c[0]), "+r"(c[1]), "+r"(c[2]), "+r"(c[3])
    : "r"(a[0]), "r"(a[1]), "r"(a[2]), "r"(a[3]), "r"(b0), "r"(b1));
}
__device__ __forceinline__ void ldmx4(uint32_t& t0, uint32_t& t1, uint32_t& t2, uint32_t& t3, uint32_t addr){
  asm volatile("ldmatrix.sync.aligned.m8n8.x4.shared.b16 {%0,%1,%2,%3}, [%4];\n"
    : "=r"(t0), "=r"(t1), "=r"(t2), "=r"(t3) : "r"(addr));
}
__device__ __forceinline__ void ldmx4t(uint32_t& t0, uint32_t& t1, uint32_t& t2, uint32_t& t3, uint32_t addr){
  asm volatile("ldmatrix.sync.aligned.m8n8.x4.trans.shared.b16 {%0,%1,%2,%3}, [%4];\n"
    : "=r"(t0), "=r"(t1), "=r"(t2), "=r"(t3) : "r"(addr));
}
#define CP16(dst, src) asm volatile("cp.async.cg.shared.global [%0], [%1], 16;\n" :: "r"(dst), "l"(src) : "memory")

#define KPITCH 144
#define VPITCH 272
#define SK_OFF(st) ((st)*64*KPITCH)
#define SV_OFF(st) (2*64*KPITCH + (st)*64*VPITCH)
#define SMEM_TOTAL (2*64*KPITCH + 2*64*VPITCH)   // 53248

// ---------------- main attention kernel (persistent, 4 CTA/SM, single-barrier loop) ----------------
__global__ void __launch_bounds__(128, 4)
attn_kernel(const float* __restrict__ qsrc,
            const int* __restrict__ wlp, const int* __restrict__ wrp,
            float* __restrict__ out){
  extern __shared__ char smem[];
  __shared__ int s_next;
  __shared__ float qred[4];
  const uint32_t smem_b = (uint32_t)__cvta_generic_to_shared(smem);

  const int tid = threadIdx.x, wid = tid >> 5, lane = tid & 31;
  const int r   = lane >> 2, q2 = (lane & 3) * 2, c4 = (lane & 3) * 4;
  const int wl = *wlp, wr = *wrp;
  const int ldm_g = lane >> 3;
  const uint32_t kfrag_off = (uint32_t)(((ldm_g >> 1)*8 + (lane & 7))*KPITCH + (ldm_g & 1)*16);
  const int jrow = lane & 15;
  const int dsel = (lane & 16) ? 8 : 0;
  const int qrow = wid*16 + r;

  int wi = blockIdx.x;
  while (wi < N_ITEMS){
    const int q_ord = wi >> 5;
    const int bh = wi & 31;
    const int xq = (q_ord & 1) ? (16 + (q_ord >> 1)) : (15 - (q_ord >> 1));
    const int i0 = xq * 64;
    const int b = bh >> 4, h = bh & 15;

    const signed char* Kg = g_k8 + (size_t)bh*SS*DD;
    const __half*      Vg = g_v16 + (size_t)bh*SS*DD;

    int jlo = (wl >= 0) ? max(0, i0 - wl) : 0;
    int jhi = (wr >= 0) ? min(SS-1, i0 + 63 + wr) : SS-1;
    const int jloT = jlo & ~63;
    const int nt = ((jhi - jloT) >> 6) + 1;

    auto issue = [&](int st, int j0){
      uint32_t kb = smem_b + SK_OFF(st);
      const signed char* kg = Kg + (size_t)j0*128;
      #pragma unroll
      for (int c = tid; c < 512; c += 128){
        int row = c >> 3, seg = c & 7;
        CP16(kb + row*KPITCH + seg*16, kg + row*128 + seg*16);
      }
      uint32_t vb = smem_b + SV_OFF(st);
      const __half* vg = Vg + (size_t)j0*128;
      #pragma unroll
      for (int c = tid; c < 1024; c += 128){
        int row = c >> 4, seg = c & 15;
        CP16(vb + row*VPITCH + seg*16, (const char*)vg + row*256 + seg*16);
      }
      asm volatile("cp.async.commit_group;\n" ::: "memory");
    };

    issue(0, jloT);   // tile-0 load overlaps Q quantization below

    // ---- fused Q quantization: f32 gmem -> int8 afrag (bit-identical to ref) ----
    const float* row0 = qsrc + ((size_t)b*SS + i0 + qrow)*HID + h*DD;
    const float* row1 = row0 + (size_t)8*HID;
    float amax = 0.f;
    #pragma unroll
    for (int kc = 0; kc < 4; kc++){
      #pragma unroll
      for (int j = 0; j < 4; j++){
        const float* rp = (j & 1) ? row1 : row0;
        int col = kc*32 + c4 + ((j & 2) ? 16 : 0);
        float4 x = *(const float4*)(rp + col);
        amax = fmaxf(amax, fmaxf(fmaxf(fabsf(x.x), fabsf(x.y)), fmaxf(fabsf(x.z), fabsf(x.w))));
      }
    }
    #pragma unroll
    for (int o = 16; o > 0; o >>= 1)
      amax = fmaxf(amax, __shfl_xor_sync(0xffffffffu, amax, o));
    if (lane == 0) qred[wid] = amax;
    __syncthreads();
    const float qscale = fmaxf(fmaxf(qred[wid], qred[wid ^ 1]) / 127.0f, 1e-8f);
    uint32_t afrag[4][4];
    #pragma unroll
    for (int kc = 0; kc < 4; kc++){
      #pragma unroll
      for (int j = 0; j < 4; j++){
        const float* rp = (j & 1) ? row1 : row0;
        int col = kc*32 + c4 + ((j & 2) ? 16 : 0);
        float4 x = *(const float4*)(rp + col);   // L1-resident reload
        int b0 = (int)fminf(fmaxf(rintf(x.x / qscale), -127.f), 127.f);
        int b1 = (int)fminf(fmaxf(rintf(x.y / qscale), -127.f), 127.f);
        int b2 = (int)fminf(fmaxf(rintf(x.z / qscale), -127.f), 127.f);
        int b3 = (int)fminf(fmaxf(rintf(x.w / qscale), -127.f), 127.f);
        afrag[kc][j] = (uint32_t)(b0 & 0xff) | ((uint32_t)(b1 & 0xff) << 8)
                     | ((uint32_t)(b2 & 0xff) << 16) | ((uint32_t)(b3 & 0xff) << 24);
      }
    }

    const float qsl = qscale * SM_SCALE_L2E;
    const int i_r0 = i0 + qrow, i_r1 = i_r0 + 8;
    const int lo0 = (wl < 0) ? -0x40000000 : i_r0 - wl;
    const int hi0 = (wr < 0) ?  0x40000000 : i_r0 + wr;
    const int lo1 = (wl < 0) ? -0x40000000 : i_r1 - wl;
    const int hi1 = (wr < 0) ?  0x40000000 : i_r1 + wr;

    float of[16][4];
    #pragma unroll
    for (int n = 0; n < 16; n++){ of[n][0]=0.f; of[n][1]=0.f; of[n][2]=0.f; of[n][3]=0.f; }
    float m0 = -1e30f, m1 = -1e30f, l0 = 0.f, l1 = 0.f;

    float ksc = g_kscale[bh*(SS/64) + (jloT >> 6)];

    for (int it = 0; it < nt; it++){
      const int j0 = jloT + it*64;
      const int st = it & 1;
      // single-barrier pipeline: wait own tile -> barrier -> issue next -> compute
      asm volatile("cp.async.wait_group 0;\n" ::: "memory");
      __syncthreads();
      if (it + 1 < nt) issue(st ^ 1, j0 + 64);

      const float dq = qsl * ksc;
      if (it + 1 < nt) ksc = g_kscale[bh*(SS/64) + ((j0 + 64) >> 6)];

      // --- S = Q K^T (int8 MMA, exact); B-frags via ldmatrix.x4 ---
      int acc[8][4];
      #pragma unroll
      for (int n = 0; n < 8; n++){ acc[n][0]=0; acc[n][1]=0; acc[n][2]=0; acc[n][3]=0; }
      const uint32_t kfb = smem_b + SK_OFF(st) + kfrag_off;
      #pragma unroll
      for (int m = 0; m < 16; m++){
        const int kc = m >> 2, nfp = m & 3;
        uint32_t b0, b1, b2, b3;
        ldmx4(b0, b1, b2, b3, kfb + nfp*(16*KPITCH) + kc*32);
        mma_s8(acc[nfp*2    ], afrag[kc], b0, b1);
        mma_s8(acc[nfp*2 + 1], afrag[kc], b2, b3);
      }

      const bool full = ((wl < 0) || (j0 >= i0 + 63 - wl)) && ((wr < 0) || (j0 + 63 <= i0 + wr));

      // --- pass 1: row max (int domain on full tiles) ---
      float mt0, mt1;
      if (full){
        int iA0[4], iA1[4];
        #pragma unroll
        for (int p = 0; p < 4; p++){
          iA0[p] = max(max(acc[2*p][0], acc[2*p][1]), max(acc[2*p+1][0], acc[2*p+1][1]));
          iA1[p] = max(max(acc[2*p][2], acc[2*p][3]), max(acc[2*p+1][2], acc[2*p+1][3]));
        }
        mt0 = __int2float_rn(max(max(iA0[0], iA0[1]), max(iA0[2], iA0[3]))) * dq;
        mt1 = __int2float_rn(max(max(iA1[0], iA1[1]), max(iA1[2], iA1[3]))) * dq;
      } else {
        mt0 = -INFINITY; mt1 = -INFINITY;
        #pragma unroll
        for (int nf = 0; nf < 8; nf++){
          int jc = j0 + nf*8 + q2;
          float s00 = (jc   >= lo0 && jc   <= hi0) ? __int2float_rn(acc[nf][0]) * dq : -INFINITY;
          float s01 = (jc+1 >= lo0 && jc+1 <= hi0) ? __int2float_rn(acc[nf][1]) * dq : -INFINITY;
          float s10 = (jc   >= lo1 && jc   <= hi1) ? __int2float_rn(acc[nf][2]) * dq : -INFINITY;
          float s11 = (jc+1 >= lo1 && jc+1 <= hi1) ? __int2float_rn(acc[nf][3]) * dq : -INFINITY;
          mt0 = fmaxf(mt0, fmaxf(s00, s01));
          mt1 = fmaxf(mt1, fmaxf(s10, s11));
        }
      }
      mt0 = fmaxf(mt0, __shfl_xor_sync(0xffffffffu, mt0, 1));
      mt0 = fmaxf(mt0, __shfl_xor_sync(0xffffffffu, mt0, 2));
      mt1 = fmaxf(mt1, __shfl_xor_sync(0xffffffffu, mt1, 1));
      mt1 = fmaxf(mt1, __shfl_xor_sync(0xffffffffu, mt1, 2));

      const bool raise = (mt0 > m0) || (mt1 > m1);
      const float mn0 = fmaxf(m0, mt0), mn1 = fmaxf(m1, mt1);
      const float a0 = ex2(m0 - mn0), a1 = ex2(m1 - mn1);
      if (__ballot_sync(0xffffffffu, raise)){
        #pragma unroll
        for (int n = 0; n < 16; n++){
          of[n][0]*=a0; of[n][1]*=a0; of[n][2]*=a1; of[n][3]*=a1;
        }
      }

      // --- pass 2 (streamed): per kc-chunk exp+pack then PV ---
      const uint32_t svb = smem_b + SV_OFF(st);
      float t0 = 0.f, t1 = 0.f;
      #pragma unroll
      for (int kc = 0; kc < 4; kc++){
        float e0[4], e1[4];
        if (full){
          #pragma unroll
          for (int hnf = 0; hnf < 2; hnf++){
            const int nf = 2*kc + hnf;
            e0[2*hnf  ] = ex2(fmaf(__int2float_rn(acc[nf][0]), dq, -mn0));
            e0[2*hnf+1] = ex2(fmaf(__int2float_rn(acc[nf][1]), dq, -mn0));
            e1[2*hnf  ] = ex2(fmaf(__int2float_rn(acc[nf][2]), dq, -mn1));
            e1[2*hnf+1] = ex2(fmaf(__int2float_rn(acc[nf][3]), dq, -mn1));
          }
        } else {
          #pragma unroll
          for (int hnf = 0; hnf < 2; hnf++){
            const int nf = 2*kc + hnf;
            int jc = j0 + nf*8 + q2;
            float s00 = (jc   >= lo0 && jc   <= hi0) ? __int2float_rn(acc[nf][0]) * dq : -INFINITY;
            float s01 = (jc+1 >= lo0 && jc+1 <= hi0) ? __int2float_rn(acc[nf][1]) * dq : -INFINITY;
            float s10 = (jc   >= lo1 && jc   <= hi1) ? __int2float_rn(acc[nf][2]) * dq : -INFINITY;
            float s11 = (jc+1 >= lo1 && jc+1 <= hi1) ? __int2float_rn(acc[nf][3]) * dq : -INFINITY;
            e0[2*hnf  ] = ex2(s00 - mn0);
            e0[2*hnf+1] = ex2(s01 - mn0);
            e1[2*hnf  ] = ex2(s10 - mn1);
            e1[2*hnf+1] = ex2(s11 - mn1);
          }
        }
        t0 += (e0[0] + e0[1]) + (e0[2] + e0[3]);
        t1 += (e1[0] + e1[1]) + (e1[2] + e1[3]);
        uint32_t pfrag[4];
        {
          __half2 p0 = __floats2half2_rn(e0[0], e0[1]);
          __half2 p1 = __floats2half2_rn(e1[0], e1[1]);
          __half2 p2 = __floats2half2_rn(e0[2], e0[3]);
          __half2 p3 = __floats2half2_rn(e1[2], e1[3]);
          pfrag[0] = *(uint32_t*)&p0; pfrag[1] = *(uint32_t*)&p1;
          pfrag[2] = *(uint32_t*)&p2; pfrag[3] = *(uint32_t*)&p3;
        }
        #pragma unroll
        for (int dc = 0; dc < 8; dc++){
          uint32_t addr = svb + (kc*16 + jrow)*VPITCH + (dc*16 + dsel)*2;
          uint32_t v0, v1, v2, v3;
          ldmx4t(v0, v1, v2, v3, addr);
          mma16816(of[dc*2    ], pfrag, v0, v1);
          mma16816(of[dc*2 + 1], pfrag, v2, v3);
        }
      }
      l0 = l0*a0 + t0; l1 = l1*a1 + t1;
      m0 = mn0; m1 = mn1;
    }

    // --- epilogue: reduce l over quad, normalize, f16-round, add v_mean ---
    l0 += __shfl_xor_sync(0xffffffffu, l0, 1);
    l0 += __shfl_xor_sync(0xffffffffu, l0, 2);
    l1 += __shfl_xor_sync(0xffffffffu, l1, 1);
    l1 += __shfl_xor_sync(0xffffffffu, l1, 2);
    float inv0 = 1.0f / l0, inv1 = 1.0f / l1;
    float* ob = out + ((size_t)b*SS)*HID + h*DD;
    const float* vm = g_vmean + bh*DD;
    #pragma unroll
    for (int n = 0; n < 16; n++){
      int d0 = n*8 + q2;
      float2 o0, o1;
      o0.x = __half2float(__float2half_rn(of[n][0]*inv0)) + vm[d0];
      o0.y = __half2float(__float2half_rn(of[n][1]*inv0)) + vm[d0+1];
      o1.x = __half2float(__float2half_rn(of[n][2]*inv1)) + vm[d0];
      o1.y = __half2float(__float2half_rn(of[n][3]*inv1)) + vm[d0+1];
      *(float2*)(ob + (size_t)i_r0*HID + d0) = o0;
      *(float2*)(ob + (size_t)i_r1*HID + d0) = o1;
    }

    // --- grab next work item ---
    __syncthreads();   // all threads done with smem stages before next item's issue
    if (tid == 0) s_next = atomicAdd(&g_wq, 1);
    __syncthreads();
    wi = s_next;
  }
}

// ---------------- launch ----------------
extern "C" void kernel_launch(void* const* d_in, const int* in_sizes, int n_in,
                              void* d_out, int out_size){
  const float* q = (const float*)d_in[0];
  const float* k = (const float*)d_in[1];
  const float* v = (const float*)d_in[2];
  const int* wl  = (const int*)d_in[3];
  const int* wr  = (const int*)d_in[4];
  float* out = (float*)d_out;

  cudaFuncSetAttribute(attn_kernel, cudaFuncAttributeMaxDynamicSharedMemorySize, SMEM_TOTAL);

  pre_k0<<<dim3(16, BB*HH), 256>>>(k, v);
  pre_k2<<<dim3(64, BB*HH), 256>>>(k, v);
  attn_kernel<<<ATTN_GRID, 128, SMEM_TOTAL>>>(q, wl, wr, out);
}